// round 1
// baseline (speedup 1.0000x reference)
#include <cuda_runtime.h>
#include <stdint.h>

// ---------------------------------------------------------------------------
// ToDenseBEVConvolution: out[b][c][x][y] += sum_i features[n][i] * K[z_n][i][c]
// for every point n with coords (x, z, y, b). C_IN = C_OUT = 64, 32 kernels,
// BEV 256x256, batch 4, N = 100000.
//
// Strategy: bucket points by z (only 32 distinct 64x64 matrices), then run a
// register-blocked 64x64 tile GEMM per bucket tile with K staged in SMEM, and
// scatter-add results with atomics.
// ---------------------------------------------------------------------------

#define C_IN    64
#define C_OUT   64
#define BEV_X   256
#define BEV_Y   256
#define TILE_P  64
#define NZ_MAX  64
#define N_MAX   (1 << 20)
#define TILES_MAX (N_MAX / TILE_P + NZ_MAX + 2)
#define FS 68   // padded row stride (floats) for transposed feature tile

// ---- scratch (no allocations allowed) ----
__device__ int g_counts[NZ_MAX];
__device__ int g_cursor[NZ_MAX];
__device__ int g_ntiles;
__device__ int g_is64;
__device__ int g_bucket[N_MAX];   // original point index, bucket-ordered
__device__ int g_base[N_MAX];     // flat output base (b*C_OUT*65536 + x*256 + y)
__device__ int g_tile_z[TILES_MAX];
__device__ int g_tile_start[TILES_MAX];
__device__ int g_tile_cnt[TILES_MAX];

// ---------------------------------------------------------------------------
// Detect coords dtype: int64 (all hi-words zero since coord values < 256) vs
// int32 (hi-words would be the interleaved z/b values — essentially never all
// zero across 32 samples).
// ---------------------------------------------------------------------------
__global__ void k_detect(const void* coords) {
    const long long* c64 = (const long long*)coords;
    bool hi_zero = ((c64[threadIdx.x] >> 32) == 0);
    unsigned ok = __ballot_sync(0xffffffffu, hi_zero);
    if (threadIdx.x == 0) g_is64 = (ok == 0xffffffffu) ? 1 : 0;
}

__device__ __forceinline__ void load_coord(const void* coords, int n,
                                           int& x, int& z, int& y, int& b) {
    if (g_is64) {
        const long long* p = (const long long*)coords + 4ll * n;
        x = (int)p[0]; z = (int)p[1]; y = (int)p[2]; b = (int)p[3];
    } else {
        const int* p = (const int*)coords + 4 * n;
        x = p[0]; z = p[1]; y = p[2]; b = p[3];
    }
}

// ---------------------------------------------------------------------------
// Zero output (float4) + zero bucket counters.
// ---------------------------------------------------------------------------
__global__ void k_zero(float4* out4, int n4) {
    int i = blockIdx.x * blockDim.x + threadIdx.x;
    if (i < n4) out4[i] = make_float4(0.f, 0.f, 0.f, 0.f);
    if (blockIdx.x == 0 && threadIdx.x < NZ_MAX) {
        g_counts[threadIdx.x] = 0;
        if (threadIdx.x == 0) g_ntiles = 0;
    }
}

// ---------------------------------------------------------------------------
// Histogram over z buckets.
// ---------------------------------------------------------------------------
__global__ void k_hist(const void* coords, const int* stride_p, int n) {
    int i = blockIdx.x * blockDim.x + threadIdx.x;
    if (i >= n) return;
    int stride = max(*stride_p, 1);
    int x, z, y, b;
    load_coord(coords, i, x, z, y, b);
    atomicAdd(&g_counts[z / stride], 1);
}

// ---------------------------------------------------------------------------
// Warp-scan offsets + build tile descriptors. One warp.
// ---------------------------------------------------------------------------
__global__ void k_scan(int nz) {
    int lane = threadIdx.x;                 // 0..31
    int cnt   = (lane < nz) ? g_counts[lane] : 0;
    int tiles = (cnt + TILE_P - 1) / TILE_P;
    int coff = cnt, toff = tiles;
    #pragma unroll
    for (int d = 1; d < 32; d <<= 1) {
        int v = __shfl_up_sync(0xffffffffu, coff, d);
        int w = __shfl_up_sync(0xffffffffu, toff, d);
        if (lane >= d) { coff += v; toff += w; }
    }
    int cstart = coff - cnt;
    int tstart = toff - tiles;
    if (lane < nz) {
        g_cursor[lane] = cstart;
        for (int s = 0, ti = tstart; s < cnt; s += TILE_P, ti++) {
            g_tile_z[ti]     = lane;
            g_tile_start[ti] = cstart + s;
            g_tile_cnt[ti]   = min(TILE_P, cnt - s);
        }
    }
    if (lane == 31) g_ntiles = toff;
}

// ---------------------------------------------------------------------------
// Scatter point indices into buckets; precompute flat output base.
// ---------------------------------------------------------------------------
__global__ void k_scatter(const void* coords, const int* stride_p, int n) {
    int i = blockIdx.x * blockDim.x + threadIdx.x;
    if (i >= n) return;
    int stride = max(*stride_p, 1);
    int x, z, y, b;
    load_coord(coords, i, x, z, y, b);
    int zq = z / stride;
    int pos = atomicAdd(&g_cursor[zq], 1);
    g_bucket[pos] = i;
    g_base[pos]   = b * (C_OUT * BEV_X * BEV_Y) + (x / stride) * BEV_Y + (y / stride);
}

// ---------------------------------------------------------------------------
// Main: one block = one tile of up to 64 points sharing kernel matrix z.
// 256 threads, each computes a 4x4 (points x channels) register block.
// ---------------------------------------------------------------------------
__global__ __launch_bounds__(256, 6)
void k_main(const float* __restrict__ features,
            const float* __restrict__ kern,
            float* __restrict__ out) {
    int tile = blockIdx.x;
    if (tile >= g_ntiles) return;

    __shared__ float Ks[C_IN * C_OUT];      // Ks[i*64 + c]     16 KB
    __shared__ float Fs[C_IN * FS];         // Fs[i*FS + p]     17 KB (transposed)
    __shared__ int   base_s[TILE_P];

    int tid   = threadIdx.x;
    int z     = g_tile_z[tile];
    int start = g_tile_start[tile];
    int cnt   = g_tile_cnt[tile];

    // Stage K[z] (4096 floats) via float4
    {
        const float4* k4 = (const float4*)(kern + (size_t)z * C_IN * C_OUT);
        float4* ks4 = (float4*)Ks;
        #pragma unroll
        for (int t = tid; t < C_IN * C_OUT / 4; t += 256) ks4[t] = k4[t];
    }
    // Stage transposed features: Fs[i][p] = features[pt_p][i]
    {
        #pragma unroll
        for (int k = 0; k < 4; k++) {
            int t  = tid + k * 256;          // 1024 tasks: (p, iv)
            int p  = t >> 4;
            int iv = t & 15;
            float4 f = make_float4(0.f, 0.f, 0.f, 0.f);
            if (p < cnt) {
                int pt = g_bucket[start + p];
                f = *(const float4*)(features + (size_t)pt * C_IN + iv * 4);
            }
            int r = iv * 4;
            Fs[(r + 0) * FS + p] = f.x;
            Fs[(r + 1) * FS + p] = f.y;
            Fs[(r + 2) * FS + p] = f.z;
            Fs[(r + 3) * FS + p] = f.w;
        }
    }
    if (tid < TILE_P)
        base_s[tid] = (tid < cnt) ? g_base[start + tid] : -1;
    __syncthreads();

    int tc = tid & 15;    // channel group
    int tp = tid >> 4;    // point group
    float acc[4][4];
    #pragma unroll
    for (int a = 0; a < 4; a++)
        #pragma unroll
        for (int c = 0; c < 4; c++) acc[a][c] = 0.f;

    #pragma unroll
    for (int i = 0; i < C_IN; i++) {
        float4 a = *(const float4*)&Fs[i * FS + tp * 4];
        float4 b = *(const float4*)&Ks[i * C_OUT + tc * 4];
        acc[0][0] += a.x * b.x; acc[0][1] += a.x * b.y; acc[0][2] += a.x * b.z; acc[0][3] += a.x * b.w;
        acc[1][0] += a.y * b.x; acc[1][1] += a.y * b.y; acc[1][2] += a.y * b.z; acc[1][3] += a.y * b.w;
        acc[2][0] += a.z * b.x; acc[2][1] += a.z * b.y; acc[2][2] += a.z * b.z; acc[2][3] += a.z * b.w;
        acc[3][0] += a.w * b.x; acc[3][1] += a.w * b.y; acc[3][2] += a.w * b.z; acc[3][3] += a.w * b.w;
    }

    // Scatter-add 4x4 results
    #pragma unroll
    for (int pp = 0; pp < 4; pp++) {
        int p = tp * 4 + pp;
        int base = base_s[p];
        if (base < 0) continue;
        #pragma unroll
        for (int cc = 0; cc < 4; cc++) {
            int c = tc * 4 + cc;
            atomicAdd(out + base + c * (BEV_X * BEV_Y), acc[pp][cc]);
        }
    }
}

// ---------------------------------------------------------------------------
extern "C" void kernel_launch(void* const* d_in, const int* in_sizes, int n_in,
                              void* d_out, int out_size) {
    const float* features = (const float*)d_in[0];
    const float* kern     = (const float*)d_in[1];
    const void*  coords   = (const void*)d_in[2];
    const int*   stride_p = (const int*)d_in[3];
    float* out = (float*)d_out;

    int n  = in_sizes[0] / C_IN;
    int nz = in_sizes[1] / (C_IN * C_OUT);
    if (nz > NZ_MAX) nz = NZ_MAX;

    k_detect<<<1, 32>>>(coords);

    int n4 = out_size / 4;
    k_zero<<<(n4 + 255) / 256, 256>>>((float4*)out, n4);

    k_hist<<<(n + 255) / 256, 256>>>(coords, stride_p, n);
    k_scan<<<1, 32>>>(nz);
    k_scatter<<<(n + 255) / 256, 256>>>(coords, stride_p, n);

    int max_tiles = n / TILE_P + nz + 1;
    k_main<<<max_tiles, 256>>>(features, kern, out);
}

// round 2
// speedup vs baseline: 1.4250x; 1.4250x over previous
#include <cuda_runtime.h>
#include <stdint.h>

// ---------------------------------------------------------------------------
// ToDenseBEVConvolution: out[b][c][x][y] += sum_i features[n][i] * K[z_n][i][c]
// C_IN = C_OUT = 64, 32 kernel matrices, BEV 256x256, batch 4, N = 100000.
//
// Pipeline (5 launches, all graph-capturable, no allocations):
//   k_zero     : zero the 64MB output
//   k_hist     : per-block SMEM histogram over z buckets (no global atomics)
//   k_scan     : single block: per-block offsets + bucket starts + tile descs
//   k_scatter  : counting-sort scatter with SMEM cursors
//   k_main     : per-tile 64x64 register-blocked GEMM + RED scatter into BEV
// ---------------------------------------------------------------------------

#define C_IN    64
#define C_OUT   64
#define BEV_Y   256
#define BEV_XY  (256 * 256)
#define TILE_P  64
#define NZ      32
#define N_MAX   (1 << 20)
#define B_MAX   224
#define TILES_MAX (N_MAX / TILE_P + NZ + 2)
#define FS      68   // padded row stride (floats) for transposed feature tile

// ---- scratch (static device globals; no runtime allocation) ----
__device__ int g_blkcnt[B_MAX * NZ];
__device__ int g_blkoff[B_MAX * NZ];
__device__ int g_ntiles;
__device__ int g_bucket[N_MAX];   // original point index, bucket-ordered
__device__ int g_base[N_MAX];     // flat output base (b*C_OUT*65536 + x*256 + y)
__device__ int g_tile_z[TILES_MAX];
__device__ int g_tile_start[TILES_MAX];
__device__ int g_tile_cnt[TILES_MAX];

// ---------------------------------------------------------------------------
// Coords dtype detection (int64 vs int32), done redundantly per block by
// warp 0. If coords are int64, all hi-words of the first 32 qwords are zero
// (coordinate values < 256). If int32, the hi-words contain z/b interleaved
// values and coords[0].b is forced to BATCH-1 != 0, so the ballot fails.
// ---------------------------------------------------------------------------
__device__ __forceinline__ int detect_is64_warp(const void* coords) {
    const long long* c = (const long long*)coords;
    bool hz = ((c[threadIdx.x & 31] >> 32) == 0);
    unsigned m = __ballot_sync(0xffffffffu, hz);
    return (m == 0xffffffffu) ? 1 : 0;
}

// ---------------------------------------------------------------------------
__global__ void k_zero(float4* out4, int n4) {
    int i = blockIdx.x * blockDim.x + threadIdx.x;
    if (i < n4) out4[i] = make_float4(0.f, 0.f, 0.f, 0.f);
}

// ---------------------------------------------------------------------------
// Per-block histogram over z buckets. SMEM atomics only.
// ---------------------------------------------------------------------------
__global__ void k_hist(const void* coords, const int* stride_p, int n, int chunk) {
    __shared__ int h[NZ];
    __shared__ int s_is64;
    int tid = threadIdx.x;
    if (tid < NZ) h[tid] = 0;
    if (tid < 32) {
        int v = detect_is64_warp(coords);
        if (tid == 0) s_is64 = v;
    }
    __syncthreads();

    int stride = max(*stride_p, 1);
    int lo = blockIdx.x * chunk;
    int hi = min(lo + chunk, n);
    if (s_is64) {
        const long long* c = (const long long*)coords;
        for (int i = lo + tid; i < hi; i += 256)
            atomicAdd(&h[(int)c[4ll * i + 1] / stride], 1);
    } else {
        const int* c = (const int*)coords;
        for (int i = lo + tid; i < hi; i += 256)
            atomicAdd(&h[c[4 * i + 1] / stride], 1);
    }
    __syncthreads();
    if (tid < NZ) g_blkcnt[blockIdx.x * NZ + tid] = h[tid];
}

// ---------------------------------------------------------------------------
// Single-block scan: per-(block,z) exclusive offsets, bucket starts, and
// parallel tile-descriptor construction.
// ---------------------------------------------------------------------------
__global__ void k_scan(int B) {
    __shared__ int s[B_MAX * NZ];          // 28 KB
    __shared__ int bstart[NZ];
    __shared__ int bcnt[NZ];
    __shared__ int tstart[NZ + 1];
    int tid = threadIdx.x;

    for (int t = tid; t < B * NZ; t += 1024) s[t] = g_blkcnt[t];
    __syncthreads();

    if (tid < NZ) {                         // per-z exclusive scan over blocks
        int z = tid, run = 0;
        for (int b = 0; b < B; b++) {
            int v = s[b * NZ + z];
            s[b * NZ + z] = run;
            run += v;
        }
        bcnt[z] = run;
    }
    __syncthreads();

    if (tid < 32) {                         // warp scan: bucket + tile offsets
        int z = tid;
        int c  = bcnt[z];
        int tl = (c + TILE_P - 1) / TILE_P;
        int co = c, to = tl;
        #pragma unroll
        for (int d = 1; d < 32; d <<= 1) {
            int v = __shfl_up_sync(0xffffffffu, co, d);
            int w = __shfl_up_sync(0xffffffffu, to, d);
            if (z >= d) { co += v; to += w; }
        }
        bstart[z] = co - c;
        tstart[z] = to - tl;
        if (z == 31) { tstart[NZ] = to; g_ntiles = to; }
    }
    __syncthreads();

    for (int t = tid; t < B * NZ; t += 1024) {
        int z = t & (NZ - 1);
        g_blkoff[t] = s[t] + bstart[z];
    }

    int ntiles = tstart[NZ];
    for (int t = tid; t < ntiles; t += 1024) {
        int lo = 0, hi = NZ - 1;            // largest z with tstart[z] <= t
        while (lo < hi) {
            int mid = (lo + hi + 1) >> 1;
            if (tstart[mid] <= t) lo = mid; else hi = mid - 1;
        }
        int local = t - tstart[lo];
        g_tile_z[t]     = lo;
        g_tile_start[t] = bstart[lo] + local * TILE_P;
        g_tile_cnt[t]   = min(TILE_P, bcnt[lo] - local * TILE_P);
    }
}

// ---------------------------------------------------------------------------
// Counting-sort scatter: SMEM cursors, no global atomics.
// ---------------------------------------------------------------------------
__global__ void k_scatter(const void* coords, const int* stride_p, int n, int chunk) {
    __shared__ int cur[NZ];
    __shared__ int s_is64;
    int tid = threadIdx.x;
    if (tid < NZ) cur[tid] = g_blkoff[blockIdx.x * NZ + tid];
    if (tid < 32) {
        int v = detect_is64_warp(coords);
        if (tid == 0) s_is64 = v;
    }
    __syncthreads();

    int stride = max(*stride_p, 1);
    int lo = blockIdx.x * chunk;
    int hi = min(lo + chunk, n);
    for (int i = lo + tid; i < hi; i += 256) {
        int x, z, y, b;
        if (s_is64) {
            const long long* p = (const long long*)coords + 4ll * i;
            x = (int)p[0]; z = (int)p[1]; y = (int)p[2]; b = (int)p[3];
        } else {
            const int* p = (const int*)coords + 4 * i;
            x = p[0]; z = p[1]; y = p[2]; b = p[3];
        }
        int zq  = z / stride;
        int pos = atomicAdd(&cur[zq], 1);
        g_bucket[pos] = i;
        g_base[pos]   = b * (C_OUT * BEV_XY) + (x / stride) * BEV_Y + (y / stride);
    }
}

// ---------------------------------------------------------------------------
// Main: one block = one tile of up to 64 points sharing kernel matrix z.
// 256 threads, each computes a 4x4 (points x channels) register block.
// ---------------------------------------------------------------------------
__global__ __launch_bounds__(256, 6)
void k_main(const float* __restrict__ features,
            const float* __restrict__ kern,
            float* __restrict__ out) {
    int tile = blockIdx.x;
    if (tile >= g_ntiles) return;

    __shared__ float Ks[C_IN * C_OUT];      // Ks[i*64 + c]     16 KB
    __shared__ float Fs[C_IN * FS];         // Fs[i*FS + p]     17 KB (transposed)
    __shared__ int   base_s[TILE_P];

    int tid   = threadIdx.x;
    int z     = g_tile_z[tile];
    int start = g_tile_start[tile];
    int cnt   = g_tile_cnt[tile];

    // Stage K[z] (4096 floats) via float4
    {
        const float4* k4 = (const float4*)(kern + (size_t)z * C_IN * C_OUT);
        float4* ks4 = (float4*)Ks;
        #pragma unroll
        for (int t = tid; t < C_IN * C_OUT / 4; t += 256) ks4[t] = k4[t];
    }
    // Stage transposed features: Fs[i][p] = features[pt_p][i]
    {
        #pragma unroll
        for (int k = 0; k < 4; k++) {
            int t  = tid + k * 256;          // 1024 tasks: (p, iv)
            int p  = t >> 4;
            int iv = t & 15;
            float4 f = make_float4(0.f, 0.f, 0.f, 0.f);
            if (p < cnt) {
                int pt = g_bucket[start + p];
                f = *(const float4*)(features + (size_t)pt * C_IN + iv * 4);
            }
            int r = iv * 4;
            Fs[(r + 0) * FS + p] = f.x;
            Fs[(r + 1) * FS + p] = f.y;
            Fs[(r + 2) * FS + p] = f.z;
            Fs[(r + 3) * FS + p] = f.w;
        }
    }
    if (tid < TILE_P)
        base_s[tid] = (tid < cnt) ? g_base[start + tid] : -1;
    __syncthreads();

    int tc = tid & 15;    // channel group
    int tp = tid >> 4;    // point group
    float acc[4][4];
    #pragma unroll
    for (int a = 0; a < 4; a++)
        #pragma unroll
        for (int c = 0; c < 4; c++) acc[a][c] = 0.f;

    #pragma unroll 8
    for (int i = 0; i < C_IN; i++) {
        float4 a = *(const float4*)&Fs[i * FS + tp * 4];
        float4 b = *(const float4*)&Ks[i * C_OUT + tc * 4];
        acc[0][0] += a.x * b.x; acc[0][1] += a.x * b.y; acc[0][2] += a.x * b.z; acc[0][3] += a.x * b.w;
        acc[1][0] += a.y * b.x; acc[1][1] += a.y * b.y; acc[1][2] += a.y * b.z; acc[1][3] += a.y * b.w;
        acc[2][0] += a.z * b.x; acc[2][1] += a.z * b.y; acc[2][2] += a.z * b.z; acc[2][3] += a.z * b.w;
        acc[3][0] += a.w * b.x; acc[3][1] += a.w * b.y; acc[3][2] += a.w * b.z; acc[3][3] += a.w * b.w;
    }

    // Scatter-add 4x4 results (REDs: atomicAdd with unused return)
    #pragma unroll
    for (int pp = 0; pp < 4; pp++) {
        int p = tp * 4 + pp;
        int base = base_s[p];
        if (base < 0) continue;
        #pragma unroll
        for (int cc = 0; cc < 4; cc++) {
            int c = tc * 4 + cc;
            atomicAdd(out + base + c * BEV_XY, acc[pp][cc]);
        }
    }
}

// ---------------------------------------------------------------------------
extern "C" void kernel_launch(void* const* d_in, const int* in_sizes, int n_in,
                              void* d_out, int out_size) {
    const float* features = (const float*)d_in[0];
    const float* kern     = (const float*)d_in[1];
    const void*  coords   = (const void*)d_in[2];
    const int*   stride_p = (const int*)d_in[3];
    float* out = (float*)d_out;

    int n = in_sizes[0] / C_IN;
    if (n > N_MAX) n = N_MAX;

    // chunking for hist/scatter: B blocks, chunk multiple of 256, B <= B_MAX
    int B = (n + 1023) / 1024;
    if (B > B_MAX) B = B_MAX;
    if (B < 1) B = 1;
    int chunk = (((n + B - 1) / B) + 255) & ~255;
    B = (n + chunk - 1) / chunk;

    int n4 = out_size / 4;
    k_zero<<<(n4 + 255) / 256, 256>>>((float4*)out, n4);

    k_hist<<<B, 256>>>(coords, stride_p, n, chunk);
    k_scan<<<1, 1024>>>(B);
    k_scatter<<<B, 256>>>(coords, stride_p, n, chunk);

    int max_tiles = n / TILE_P + NZ + 1;
    k_main<<<max_tiles, 256>>>(features, kern, out);
}